// round 1
// baseline (speedup 1.0000x reference)
#include <cuda_runtime.h>
#include <cstdint>

#define B_   4
#define N_   50000
#define F_   64
#define E_   800000
#define ROWS_TOTAL (B_ * N_)          // 200000
#define OUT_ELEMS  (B_ * N_ * F_)     // 12800000

// Static device scratch for the dense pre-activations (allowed scratch path).
__device__ float g_pre1[(size_t)ROWS_TOTAL * F_];
__device__ float g_pre2[(size_t)ROWS_TOTAL * F_];

// ---------------------------------------------------------------------------
// out[b,n,f] = bias[f]
// ---------------------------------------------------------------------------
__global__ void init_kernel(float* __restrict__ out, const float* __restrict__ bias) {
    int i = blockIdx.x * blockDim.x + threadIdx.x;
    if (i < OUT_ELEMS) out[i] = bias[i & 63];
}

// ---------------------------------------------------------------------------
// pre1 = x @ W1, pre2 = x @ W2  (x: [ROWS_TOTAL, 64], W: [64, 64] row-major)
// 32 rows per block, 256 threads: thread = (o = tid&63, rq = tid>>6),
// each thread computes 8 rows x 1 output feature x 2 weight matrices.
// ---------------------------------------------------------------------------
__global__ __launch_bounds__(256) void gemm_kernel(const float* __restrict__ x,
                                                   const float* __restrict__ W1,
                                                   const float* __restrict__ W2) {
    __shared__ float W1s[64 * 64];
    __shared__ float W2s[64 * 64];
    __shared__ float xs[32][64];

    int tid = threadIdx.x;
    for (int i = tid; i < 64 * 64; i += 256) {
        W1s[i] = W1[i];
        W2s[i] = W2[i];
    }
    int row0 = blockIdx.x * 32;
    // load x tile: 32 rows x 64 floats = 512 float4
    const float4* xg  = (const float4*)(x + (size_t)row0 * F_);
    float4*       xsv = (float4*)&xs[0][0];
    for (int i = tid; i < 512; i += 256) xsv[i] = xg[i];
    __syncthreads();

    int o  = tid & 63;
    int rq = tid >> 6;  // 0..3, 8 rows each

    float acc1[8], acc2[8];
#pragma unroll
    for (int i = 0; i < 8; i++) { acc1[i] = 0.f; acc2[i] = 0.f; }

#pragma unroll
    for (int k = 0; k < 64; k++) {
        float w1 = W1s[k * 64 + o];
        float w2 = W2s[k * 64 + o];
#pragma unroll
        for (int i = 0; i < 8; i++) {
            float xv = xs[rq * 8 + i][k];   // broadcast within warp
            acc1[i] = fmaf(xv, w1, acc1[i]);
            acc2[i] = fmaf(xv, w2, acc2[i]);
        }
    }

#pragma unroll
    for (int i = 0; i < 8; i++) {
        size_t r = (size_t)(row0 + rq * 8 + i);
        g_pre1[r * F_ + o] = acc1[i];
        g_pre2[r * F_ + o] = acc2[i];
    }
}

// ---------------------------------------------------------------------------
// Scatter SpMM: out[b, rows[e], :] += vals[e] * pre[b, cols[e], :]
// One warp per (batch, edge). which: 0 -> g_pre1, 1 -> g_pre2.
// ---------------------------------------------------------------------------
__global__ __launch_bounds__(256) void spmm_kernel(const int* __restrict__ rows,
                                                   const int* __restrict__ cols,
                                                   const float* __restrict__ vals,
                                                   int which,
                                                   float* __restrict__ out) {
    int warp = (blockIdx.x * blockDim.x + threadIdx.x) >> 5;
    int lane = threadIdx.x & 31;
    if (warp >= B_ * E_) return;

    int b = warp / E_;
    int e = warp - b * E_;

    int   col = cols[e];
    int   row = rows[e];
    float v   = vals[e];

    const float* pre = which ? g_pre2 : g_pre1;
    const float* src = pre + ((size_t)b * N_ + col) * F_;
    float*       dst = out + ((size_t)b * N_ + row) * F_;

    atomicAdd(dst + lane,      v * src[lane]);
    atomicAdd(dst + lane + 32, v * src[lane + 32]);
}

// ---------------------------------------------------------------------------
// out = relu(out)
// ---------------------------------------------------------------------------
__global__ void relu_kernel(float* __restrict__ out) {
    int i = blockIdx.x * blockDim.x + threadIdx.x;
    if (i < OUT_ELEMS) out[i] = fmaxf(out[i], 0.f);
}

extern "C" void kernel_launch(void* const* d_in, const int* in_sizes, int n_in,
                              void* d_out, int out_size) {
    const float* x     = (const float*)d_in[0];
    const int*   rows1 = (const int*)  d_in[1];
    const int*   cols1 = (const int*)  d_in[2];
    const float* vals1 = (const float*)d_in[3];
    const int*   rows2 = (const int*)  d_in[4];
    const int*   cols2 = (const int*)  d_in[5];
    const float* vals2 = (const float*)d_in[6];
    const float* W1    = (const float*)d_in[7];
    const float* W2    = (const float*)d_in[8];
    const float* bias  = (const float*)d_in[9];
    float*       out   = (float*)d_out;

    // 1) out = bias
    init_kernel<<<(OUT_ELEMS + 1023) / 1024, 1024>>>(out, bias);

    // 2) pre1 = x@W1, pre2 = x@W2
    gemm_kernel<<<ROWS_TOTAL / 32, 256>>>(x, W1, W2);

    // 3) scatter both supports (one warp per (batch, edge))
    const int warps  = B_ * E_;                 // 3.2M warps per support
    const int blocks = (warps * 32 + 255) / 256;
    spmm_kernel<<<blocks, 256>>>(rows1, cols1, vals1, 0, out);
    spmm_kernel<<<blocks, 256>>>(rows2, cols2, vals2, 1, out);

    // 4) relu in place
    relu_kernel<<<(OUT_ELEMS + 1023) / 1024, 1024>>>(out);
}

// round 2
// speedup vs baseline: 1.1504x; 1.1504x over previous
#include <cuda_runtime.h>
#include <cstdint>

#define B_   4
#define N_   50000
#define F_   64
#define E_   800000
#define ROWS_TOTAL (B_ * N_)          // 200000
#define OUT_ELEMS  (B_ * N_ * F_)     // 12800000

// Static device scratch for the dense pre-activations.
__device__ float g_pre1[(size_t)ROWS_TOTAL * F_];
__device__ float g_pre2[(size_t)ROWS_TOTAL * F_];

// ---------------------------------------------------------------------------
// out[b,n,f] = bias[f]   (float4 vectorized)
// ---------------------------------------------------------------------------
__global__ void init_kernel(float4* __restrict__ out, const float* __restrict__ bias) {
    int i = blockIdx.x * blockDim.x + threadIdx.x;
    if (i < OUT_ELEMS / 4) {
        int f = (i & 15) * 4;  // 16 float4 per 64-feature row
        float4 v = make_float4(bias[f], bias[f + 1], bias[f + 2], bias[f + 3]);
        out[i] = v;
    }
}

// ---------------------------------------------------------------------------
// pre1 = x @ W1, pre2 = x @ W2 using packed fma.rn.f32x2 (FFMA2).
// 32 rows/block, 256 threads: thread = (o = tid&63, rq = tid>>6).
// Each thread: 8 rows (as 4 row-pairs) x 1 out feature x 2 weight matrices.
// x tile stored k-major (transposed) so row pairs load as one float2.
// ---------------------------------------------------------------------------
__global__ __launch_bounds__(256) void gemm_kernel(const float* __restrict__ x,
                                                   const float* __restrict__ W1,
                                                   const float* __restrict__ W2) {
    __shared__ float W1s[64 * 64];
    __shared__ float W2s[64 * 64];
    __shared__ float xs[64][34];   // [k][row], pad 34 -> float2 alignment + low conflicts

    int tid = threadIdx.x;
    for (int i = tid; i < 64 * 64; i += 256) {
        W1s[i] = W1[i];
        W2s[i] = W2[i];
    }
    int row0 = blockIdx.x * 32;
    const float4* xg = (const float4*)(x + (size_t)row0 * F_);
    for (int i = tid; i < 512; i += 256) {        // 32 rows x 16 float4
        float4 v = xg[i];
        int r = i >> 4;
        int k = (i & 15) * 4;
        xs[k][r] = v.x; xs[k + 1][r] = v.y; xs[k + 2][r] = v.z; xs[k + 3][r] = v.w;
    }
    __syncthreads();

    int o  = tid & 63;
    int rq = tid >> 6;           // 0..3 -> rows rq*8 .. rq*8+7
    int rbase = rq * 8;

    unsigned long long acc1[4] = {0ull, 0ull, 0ull, 0ull};   // f32x2 {0,0}
    unsigned long long acc2[4] = {0ull, 0ull, 0ull, 0ull};

#pragma unroll
    for (int k = 0; k < 64; k++) {
        float w1 = W1s[k * 64 + o];
        float w2 = W2s[k * 64 + o];
        unsigned long long w1p, w2p;
        asm("mov.b64 %0, {%1, %1};" : "=l"(w1p) : "f"(w1));
        asm("mov.b64 %0, {%1, %1};" : "=l"(w2p) : "f"(w2));
#pragma unroll
        for (int j = 0; j < 4; j++) {
            float2 xp = *(const float2*)&xs[k][rbase + 2 * j];   // broadcast in warp
            unsigned long long xpk;
            asm("mov.b64 %0, {%1, %2};" : "=l"(xpk) : "f"(xp.x), "f"(xp.y));
            asm("fma.rn.f32x2 %0, %1, %2, %0;" : "+l"(acc1[j]) : "l"(xpk), "l"(w1p));
            asm("fma.rn.f32x2 %0, %1, %2, %0;" : "+l"(acc2[j]) : "l"(xpk), "l"(w2p));
        }
    }

#pragma unroll
    for (int j = 0; j < 4; j++) {
        float lo, hi;
        size_t r = (size_t)(row0 + rbase + 2 * j);
        asm("mov.b64 {%0, %1}, %2;" : "=f"(lo), "=f"(hi) : "l"(acc1[j]));
        g_pre1[r * F_ + o] = lo;
        g_pre1[(r + 1) * F_ + o] = hi;
        asm("mov.b64 {%0, %1}, %2;" : "=f"(lo), "=f"(hi) : "l"(acc2[j]));
        g_pre2[r * F_ + o] = lo;
        g_pre2[(r + 1) * F_ + o] = hi;
    }
}

// ---------------------------------------------------------------------------
// Fused scatter SpMM for both supports:
//   out[b, rows[e], :] += vals[e] * pre[b, cols[e], :]   for b = 0..3
// One warp per (support, edge); lane handles 2 features (float2 + red.v2.f32).
// Index loads amortized over the 4 batches.
// ---------------------------------------------------------------------------
__global__ __launch_bounds__(256) void spmm_all(const int*   __restrict__ rows1,
                                                const int*   __restrict__ cols1,
                                                const float* __restrict__ vals1,
                                                const int*   __restrict__ rows2,
                                                const int*   __restrict__ cols2,
                                                const float* __restrict__ vals2,
                                                float* __restrict__ out) {
    int gw   = (blockIdx.x * blockDim.x + threadIdx.x) >> 5;
    int lane = threadIdx.x & 31;
    if (gw >= 2 * E_) return;

    const int* rows; const int* cols; const float* vals; const float* pre;
    int e;
    if (gw < E_) { e = gw;       rows = rows1; cols = cols1; vals = vals1; pre = g_pre1; }
    else         { e = gw - E_;  rows = rows2; cols = cols2; vals = vals2; pre = g_pre2; }

    int   col = __ldg(cols + e);
    int   row = __ldg(rows + e);
    float v   = __ldg(vals + e);

    const float2* src = (const float2*)(pre + (size_t)col * F_) + lane;
    float2*       dst = (float2*)(out + (size_t)row * F_) + lane;
    const size_t  bstride = (size_t)N_ * (F_ / 2);   // float2 stride per batch

#pragma unroll
    for (int b = 0; b < 4; b++) {
        float2 s = __ldg(src + b * bstride);
        float xx = v * s.x;
        float yy = v * s.y;
        asm volatile("red.global.add.v2.f32 [%0], {%1, %2};"
                     :: "l"(dst + b * bstride), "f"(xx), "f"(yy)
                     : "memory");
    }
}

// ---------------------------------------------------------------------------
// out = relu(out)  (float4 vectorized)
// ---------------------------------------------------------------------------
__global__ void relu_kernel(float4* __restrict__ out) {
    int i = blockIdx.x * blockDim.x + threadIdx.x;
    if (i < OUT_ELEMS / 4) {
        float4 v = out[i];
        v.x = fmaxf(v.x, 0.f); v.y = fmaxf(v.y, 0.f);
        v.z = fmaxf(v.z, 0.f); v.w = fmaxf(v.w, 0.f);
        out[i] = v;
    }
}

extern "C" void kernel_launch(void* const* d_in, const int* in_sizes, int n_in,
                              void* d_out, int out_size) {
    const float* x     = (const float*)d_in[0];
    const int*   rows1 = (const int*)  d_in[1];
    const int*   cols1 = (const int*)  d_in[2];
    const float* vals1 = (const float*)d_in[3];
    const int*   rows2 = (const int*)  d_in[4];
    const int*   cols2 = (const int*)  d_in[5];
    const float* vals2 = (const float*)d_in[6];
    const float* W1    = (const float*)d_in[7];
    const float* W2    = (const float*)d_in[8];
    const float* bias  = (const float*)d_in[9];
    float*       out   = (float*)d_out;

    // 1) out = bias
    init_kernel<<<(OUT_ELEMS / 4 + 255) / 256, 256>>>((float4*)out, bias);

    // 2) pre1 = x@W1, pre2 = x@W2
    gemm_kernel<<<ROWS_TOTAL / 32, 256>>>(x, W1, W2);

    // 3) both supports, all batches, one launch
    const int warps  = 2 * E_;
    const int blocks = (warps * 32 + 255) / 256;
    spmm_all<<<blocks, 256>>>(rows1, cols1, vals1, rows2, cols2, vals2, out);

    // 4) relu in place
    relu_kernel<<<(OUT_ELEMS / 4 + 255) / 256, 256>>>((float4*)out);
}

// round 3
// speedup vs baseline: 2.8624x; 2.4881x over previous
#include <cuda_runtime.h>
#include <cuda_fp16.h>
#include <cstdint>

#define B_   4
#define N_   50000
#define F_   64
#define E_   800000
#define ROWS_TOTAL (B_ * N_)          // 200000
#define OUT_ELEMS  (B_ * N_ * F_)     // 12800000
#define E2_  (2 * E_)                 // 1600000
#define N2_  (2 * N_)                 // 100000 (per-support row counters)

// ---------------------------------------------------------------------------
// Static device scratch
// ---------------------------------------------------------------------------
// pre-activations in fp16, [support][b*N+n][32 half2]  (51.2 MB total)
__device__ __half2 g_preh[2ull * ROWS_TOTAL * 32];
__device__ int     g_count[N2_];      // per (support,row) degree
__device__ int     g_cursor[N2_];     // fill cursors
__device__ int     g_offs[N2_];       // exclusive prefix (CSR row offsets)
__device__ int     g_btot[128];       // scan block totals
__device__ int     g_csr_col[E2_];
__device__ float   g_csr_val[E2_];

// ---------------------------------------------------------------------------
// zero counters
// ---------------------------------------------------------------------------
__global__ void zero_kernel() {
    int i = blockIdx.x * blockDim.x + threadIdx.x;
    if (i < N2_) { g_count[i] = 0; g_cursor[i] = 0; }
}

// ---------------------------------------------------------------------------
// histogram of destination rows, both supports
// ---------------------------------------------------------------------------
__global__ __launch_bounds__(256) void hist_kernel(const int* __restrict__ rows1,
                                                   const int* __restrict__ rows2) {
    int t = blockIdx.x * blockDim.x + threadIdx.x;
    if (t >= E2_) return;
    int r = (t < E_) ? __ldg(rows1 + t) : __ldg(rows2 + (t - E_));
    int idx = (t < E_) ? r : (N_ + r);
    atomicAdd(&g_count[idx], 1);
}

// ---------------------------------------------------------------------------
// exclusive scan of g_count (100000 ints) -> g_offs, 2-level
// ---------------------------------------------------------------------------
__global__ __launch_bounds__(256) void scan_blocks_kernel() {
    __shared__ int sm[256];
    int base = blockIdx.x * 1024 + threadIdx.x * 4;
    int v[4];
#pragma unroll
    for (int j = 0; j < 4; j++) v[j] = (base + j < N2_) ? g_count[base + j] : 0;
    int t = v[0] + v[1] + v[2] + v[3];
    sm[threadIdx.x] = t;
    __syncthreads();
    // inclusive Hillis-Steele over 256 thread sums
#pragma unroll
    for (int off = 1; off < 256; off <<= 1) {
        int add = (threadIdx.x >= off) ? sm[threadIdx.x - off] : 0;
        __syncthreads();
        sm[threadIdx.x] += add;
        __syncthreads();
    }
    int run = sm[threadIdx.x] - t;     // exclusive prefix of this thread
#pragma unroll
    for (int j = 0; j < 4; j++) {
        if (base + j < N2_) g_offs[base + j] = run;
        run += v[j];
    }
    if (threadIdx.x == 255) g_btot[blockIdx.x] = sm[255];
}

__global__ void scan_tops_kernel(int nblk) {   // single block, 128 threads
    __shared__ int sm[128];
    int t = (threadIdx.x < nblk) ? g_btot[threadIdx.x] : 0;
    sm[threadIdx.x] = t;
    __syncthreads();
#pragma unroll
    for (int off = 1; off < 128; off <<= 1) {
        int add = (threadIdx.x >= off) ? sm[threadIdx.x - off] : 0;
        __syncthreads();
        sm[threadIdx.x] += add;
        __syncthreads();
    }
    if (threadIdx.x < nblk) g_btot[threadIdx.x] = sm[threadIdx.x] - t;  // exclusive
}

__global__ void scan_apply_kernel() {
    int i = blockIdx.x * blockDim.x + threadIdx.x;
    if (i < N2_) g_offs[i] += g_btot[i >> 10];
}

// ---------------------------------------------------------------------------
// scatter edges into CSR slots
// ---------------------------------------------------------------------------
__global__ __launch_bounds__(256) void fill_kernel(const int* __restrict__ rows1,
                                                   const int* __restrict__ cols1,
                                                   const float* __restrict__ vals1,
                                                   const int* __restrict__ rows2,
                                                   const int* __restrict__ cols2,
                                                   const float* __restrict__ vals2) {
    int t = blockIdx.x * blockDim.x + threadIdx.x;
    if (t >= E2_) return;
    int r, c; float v; int idx;
    if (t < E_) {
        r = __ldg(rows1 + t); c = __ldg(cols1 + t); v = __ldg(vals1 + t);
        idx = r;
    } else {
        int e = t - E_;
        r = __ldg(rows2 + e); c = __ldg(cols2 + e); v = __ldg(vals2 + e);
        idx = N_ + r;
    }
    int slot = g_offs[idx] + atomicAdd(&g_cursor[idx], 1);
    g_csr_col[slot] = c;
    g_csr_val[slot] = v;
}

// ---------------------------------------------------------------------------
// pre1 = x@W1, pre2 = x@W2 with packed fma.rn.f32x2, store fp16.
// 32 rows/block, 256 threads: thread = (fpair = tid&31, rg = tid>>5).
// Each thread: 4 rows x 2 adjacent features x 2 supports.
// ---------------------------------------------------------------------------
__global__ __launch_bounds__(256) void gemm_kernel(const float* __restrict__ x,
                                                   const float* __restrict__ W1,
                                                   const float* __restrict__ W2) {
    __shared__ float W1s[64 * 64];
    __shared__ float W2s[64 * 64];
    __shared__ float xs[64][33];   // [k][row]

    int tid = threadIdx.x;
    for (int i = tid; i < 64 * 64; i += 256) {
        W1s[i] = W1[i];
        W2s[i] = W2[i];
    }
    int row0 = blockIdx.x * 32;
    const float4* xg = (const float4*)(x + (size_t)row0 * F_);
    for (int i = tid; i < 512; i += 256) {        // 32 rows x 16 float4
        float4 v = xg[i];
        int r = i >> 4;
        int k = (i & 15) * 4;
        xs[k][r] = v.x; xs[k + 1][r] = v.y; xs[k + 2][r] = v.z; xs[k + 3][r] = v.w;
    }
    __syncthreads();

    int fpair = tid & 31;          // feature pair index (features 2f, 2f+1)
    int rg    = tid >> 5;          // 0..7 -> rows rg*4..rg*4+3

    unsigned long long a1[4] = {0ull, 0ull, 0ull, 0ull};
    unsigned long long a2[4] = {0ull, 0ull, 0ull, 0ull};

#pragma unroll
    for (int k = 0; k < 64; k++) {
        unsigned long long w1p = *(const unsigned long long*)&W1s[k * 64 + fpair * 2];
        unsigned long long w2p = *(const unsigned long long*)&W2s[k * 64 + fpair * 2];
#pragma unroll
        for (int r = 0; r < 4; r++) {
            float xv = xs[k][rg * 4 + r];                 // warp broadcast
            unsigned long long xp;
            asm("mov.b64 %0, {%1, %1};" : "=l"(xp) : "f"(xv));
            asm("fma.rn.f32x2 %0, %1, %2, %0;" : "+l"(a1[r]) : "l"(xp), "l"(w1p));
            asm("fma.rn.f32x2 %0, %1, %2, %0;" : "+l"(a2[r]) : "l"(xp), "l"(w2p));
        }
    }

    const size_t sup_stride = (size_t)ROWS_TOTAL * 32;
#pragma unroll
    for (int r = 0; r < 4; r++) {
        size_t row = (size_t)(row0 + rg * 4 + r);
        float lo, hi;
        asm("mov.b64 {%0, %1}, %2;" : "=f"(lo), "=f"(hi) : "l"(a1[r]));
        g_preh[row * 32 + fpair] = __floats2half2_rn(lo, hi);
        asm("mov.b64 {%0, %1}, %2;" : "=f"(lo), "=f"(hi) : "l"(a2[r]));
        g_preh[sup_stride + row * 32 + fpair] = __floats2half2_rn(lo, hi);
    }
}

// ---------------------------------------------------------------------------
// Gather SpMM + bias + relu, fully fused.
// One warp per output row: both supports, all 4 batches, plain final stores.
// ---------------------------------------------------------------------------
__global__ __launch_bounds__(256) void gather_kernel(const float* __restrict__ bias,
                                                     float* __restrict__ out) {
    int gw   = (blockIdx.x * blockDim.x + threadIdx.x) >> 5;
    int lane = threadIdx.x & 31;
    if (gw >= N_) return;
    int row = gw;

    float bx = __ldg(bias + lane * 2);
    float by = __ldg(bias + lane * 2 + 1);
    float2 acc[4];
#pragma unroll
    for (int b = 0; b < 4; b++) acc[b] = make_float2(bx, by);

    const size_t sup_stride = (size_t)ROWS_TOTAL * 32;
    const size_t bstride    = (size_t)N_ * 32;

#pragma unroll
    for (int s = 0; s < 2; s++) {
        int idx   = s * N_ + row;
        int start = g_offs[idx];
        int deg   = g_count[idx];
        const __half2* pre = g_preh + (size_t)s * sup_stride;

        for (int c0 = 0; c0 < deg; c0 += 32) {
            int nc = min(32, deg - c0);
            int   colv = 0;
            float vv   = 0.f;
            if (lane < nc) {
                colv = g_csr_col[start + c0 + lane];
                vv   = g_csr_val[start + c0 + lane];
            }
            for (int i = 0; i < nc; i++) {
                int   ci = __shfl_sync(0xffffffffu, colv, i);
                float vi = __shfl_sync(0xffffffffu, vv,   i);
                const __half2* src = pre + (size_t)ci * 32 + lane;
#pragma unroll
                for (int b = 0; b < 4; b++) {
                    __half2 h = __ldg(src + (size_t)b * bstride);
                    float2 f = __half22float2(h);
                    acc[b].x = fmaf(vi, f.x, acc[b].x);
                    acc[b].y = fmaf(vi, f.y, acc[b].y);
                }
            }
        }
    }

    float2* outv = (float2*)out;
#pragma unroll
    for (int b = 0; b < 4; b++) {
        float2 o;
        o.x = fmaxf(acc[b].x, 0.f);
        o.y = fmaxf(acc[b].y, 0.f);
        outv[((size_t)b * N_ + row) * 32 + lane] = o;
    }
}

extern "C" void kernel_launch(void* const* d_in, const int* in_sizes, int n_in,
                              void* d_out, int out_size) {
    const float* x     = (const float*)d_in[0];
    const int*   rows1 = (const int*)  d_in[1];
    const int*   cols1 = (const int*)  d_in[2];
    const float* vals1 = (const float*)d_in[3];
    const int*   rows2 = (const int*)  d_in[4];
    const int*   cols2 = (const int*)  d_in[5];
    const float* vals2 = (const float*)d_in[6];
    const float* W1    = (const float*)d_in[7];
    const float* W2    = (const float*)d_in[8];
    const float* bias  = (const float*)d_in[9];
    float*       out   = (float*)d_out;

    const int nScanBlocks = (N2_ + 1023) / 1024;   // 98

    // CSR construction
    zero_kernel<<<(N2_ + 255) / 256, 256>>>();
    hist_kernel<<<(E2_ + 255) / 256, 256>>>(rows1, rows2);
    scan_blocks_kernel<<<nScanBlocks, 256>>>();
    scan_tops_kernel<<<1, 128>>>(nScanBlocks);
    scan_apply_kernel<<<(N2_ + 255) / 256, 256>>>();
    fill_kernel<<<(E2_ + 255) / 256, 256>>>(rows1, cols1, vals1, rows2, cols2, vals2);

    // dense pre-activations (fp16 output)
    gemm_kernel<<<ROWS_TOTAL / 32, 256>>>(x, W1, W2);

    // fused gather + bias + relu
    gather_kernel<<<(N_ * 32 + 255) / 256, 256>>>(bias, out);
}